// round 9
// baseline (speedup 1.0000x reference)
#include <cuda_runtime.h>
#include <math.h>

#define BB 4
#define CC 64
#define LL 16384
#define BL 65536
#define DI 128
#define DS 16
#define NKF 65
#define NIMG 256
#define NCHK 64
#define CHKS 256
#define FPIX (NKF*128)   // 8320 freq pixels per image

__device__ float d_xz [BL*256];
__device__ float d_xc [BL*DI];
__device__ float d_dbc[BL*36];
__device__ float d_dt [BL*DI];
__device__ float d_hloc[BB*DI*NCHK*DS];
__device__ float d_cd  [BB*DI*NCHK];
__device__ float d_Hst [BB*DI*NCHK*DS];
__device__ float d_ygt [BB*DI*LL];
__device__ float d_xsp [BB*CC*LL];
__device__ float d_RT  [32768*130];
__device__ float d_Cre [NIMG*FPIX];
__device__ float d_Cim [NIMG*FPIX];
__device__ float d_mag [NIMG*FPIX];
__device__ float d_M1  [NIMG*FPIX];
__device__ float d_M2  [NIMG*FPIX];
__device__ float d_Zr  [NIMG*FPIX];
__device__ float d_Zi  [NIMG*FPIX];
__device__ float d_Yr  [NIMG*FPIX];
__device__ float d_Yi  [NIMG*FPIX];
__device__ float d_xfr [BB*CC*LL];
__device__ float d_TW1 [128*130];
__device__ float d_TCOS[128*128];
__device__ float d_TSIN[128*128];
__device__ float d_TSINN[128*128];
__device__ float d_IRW1[NKF*128];
__device__ float d_IRW2[NKF*128];

__global__ void gen_tables() {
    int i = blockIdx.x*256 + threadIdx.x;
    if (i < 128*130) {
        int w = i/130, j = i%130;
        int k = (j < NKF) ? j : j-NKF;
        float s,c; sincospif((float)((w*k)&127)/64.0f, &s, &c);
        d_TW1[i] = (j < NKF) ? c : -s;
    }
    if (i < 128*128) {
        int u = i/128, h = i%128;
        float s,c; sincospif((float)((u*h)&127)/64.0f, &s, &c);
        d_TCOS[i]=c; d_TSIN[i]=s; d_TSINN[i]=-s;
    }
    if (i < NKF*128) {
        int kf = i/128, w = i%128;
        float a = (kf==0 || kf==64) ? 1.0f : 2.0f;
        float s,c; sincospif((float)((kf*w)&127)/64.0f, &s, &c);
        d_IRW1[i] =  a*c*(1.0f/16384.0f);
        d_IRW2[i] = -a*s*(1.0f/16384.0f);
    }
}

// ---------------------------------------------------------------------------
// Tiled SGEMM: C[m,n] = sum_k A[m,k]*B[k,n] (+ A2[m,k]*B2[k,n] if DUAL)
// BM x BN block tile, 256 threads as 16x16, (BM/16)x(BN/16) microtile.
// ---------------------------------------------------------------------------
template<int BM, int BN, bool DUAL>
__global__ void __launch_bounds__(256)
sgemm(const float* __restrict__ A, const float* __restrict__ A2,
      int lda_m, int lda_k, int sA,
      const float* __restrict__ B, const float* __restrict__ B2,
      int ldb_k, int ldb_n, int sB,
      float* __restrict__ C, int ldc, int sC,
      int M, int N, int K,
      const float* __restrict__ bias, int biasMode, int doRelu)
{
    constexpr int TM = BM/16, TN = BN/16;
    __shared__ float As [16][BM+4];
    __shared__ float Bs [16][BN+4];
    __shared__ float As2[DUAL?16:1][DUAL?(BM+4):1];
    __shared__ float Bs2[DUAL?16:1][DUAL?(BN+4):1];

    int bz = blockIdx.z;
    const float* Ab  = A  + (size_t)bz*sA;
    const float* Bb  = B  + (size_t)bz*sB;
    const float* A2b = DUAL ? (A2 + (size_t)bz*sA) : A;
    const float* B2b = DUAL ? (B2 + (size_t)bz*sB) : B;
    float* Cb = C + (size_t)bz*sC;

    int m0 = blockIdx.y*BM, n0 = blockIdx.x*BN;
    int tid = threadIdx.x, tx = tid&15, ty = tid>>4;

    float acc[TM][TN];
#pragma unroll
    for (int i=0;i<TM;i++)
#pragma unroll
        for (int j=0;j<TN;j++) acc[i][j]=0.f;

    for (int k0 = 0; k0 < K; k0 += 16) {
        // ---- load A tile: As[k][m] ----
        if (lda_k == 1) {
#pragma unroll
            for (int r = 0; r < BM/16; r++) {
                int idx = tid + r*256;
                int k = idx & 15, m = idx >> 4;
                int gm = m0+m, gk = k0+k;
                bool ok = (gm < M) && (gk < K);
                As[k][m] = ok ? Ab[(size_t)gm*lda_m + gk] : 0.f;
                if (DUAL) As2[k][m] = ok ? A2b[(size_t)gm*lda_m + gk] : 0.f;
            }
        } else {
#pragma unroll
            for (int r = 0; r < BM/16; r++) {
                int idx = tid + r*256;
                int m = idx & (BM-1), k = idx / BM;
                int gm = m0+m, gk = k0+k;
                bool ok = (gm < M) && (gk < K);
                As[k][m] = ok ? Ab[(size_t)gm*lda_m + (size_t)gk*lda_k] : 0.f;
                if (DUAL) As2[k][m] = ok ? A2b[(size_t)gm*lda_m + (size_t)gk*lda_k] : 0.f;
            }
        }
        // ---- load B tile: Bs[k][n] ----
        if (ldb_n == 1) {
#pragma unroll
            for (int r = 0; r < BN/16; r++) {
                int idx = tid + r*256;
                int n = idx & (BN-1), k = idx / BN;
                int gn = n0+n, gk = k0+k;
                bool ok = (gk < K) && (gn < N);
                Bs[k][n] = ok ? Bb[(size_t)gk*ldb_k + gn] : 0.f;
                if (DUAL) Bs2[k][n] = ok ? B2b[(size_t)gk*ldb_k + gn] : 0.f;
            }
        } else {
#pragma unroll
            for (int r = 0; r < BN/16; r++) {
                int idx = tid + r*256;
                int k = idx & 15, n = idx >> 4;
                int gn = n0+n, gk = k0+k;
                bool ok = (gk < K) && (gn < N);
                Bs[k][n] = ok ? Bb[(size_t)gk*ldb_k + (size_t)gn*ldb_n] : 0.f;
                if (DUAL) Bs2[k][n] = ok ? B2b[(size_t)gk*ldb_k + (size_t)gn*ldb_n] : 0.f;
            }
        }
        __syncthreads();
#pragma unroll
        for (int kk=0; kk<16; kk++) {
            float a1[TM], b1[TN];
#pragma unroll
            for (int i=0;i<TM;i+=4) *(float4*)&a1[i] = *(const float4*)&As[kk][ty*TM+i];
#pragma unroll
            for (int j=0;j<TN;j+=4) *(float4*)&b1[j] = *(const float4*)&Bs[kk][tx*TN+j];
#pragma unroll
            for (int i=0;i<TM;i++)
#pragma unroll
                for (int j=0;j<TN;j++) acc[i][j] = fmaf(a1[i], b1[j], acc[i][j]);
            if (DUAL) {
                float a2[TM], b2[TN];
#pragma unroll
                for (int i=0;i<TM;i+=4) *(float4*)&a2[i] = *(const float4*)&As2[kk][ty*TM+i];
#pragma unroll
                for (int j=0;j<TN;j+=4) *(float4*)&b2[j] = *(const float4*)&Bs2[kk][tx*TN+j];
#pragma unroll
                for (int i=0;i<TM;i++)
#pragma unroll
                    for (int j=0;j<TN;j++) acc[i][j] = fmaf(a2[i], b2[j], acc[i][j]);
            }
        }
        __syncthreads();
    }
#pragma unroll
    for (int i=0;i<TM;i++) {
        int m = m0 + ty*TM + i;
        if (m >= M) continue;
#pragma unroll
        for (int j=0;j<TN;j++) {
            int n = n0 + tx*TN + j;
            if (n >= N) continue;
            float v = acc[i][j];
            if (biasMode == 1) v += bias[n];
            else if (biasMode == 2) v += bias[m];
            if (doRelu) v = fmaxf(v, 0.f);
            Cb[(size_t)m*ldc + n] = v;
        }
    }
}

__global__ void conv_silu_k(const float* __restrict__ xz, const float* __restrict__ cw,
                            const float* __restrict__ cb, float* __restrict__ xc)
{
    int idx = blockIdx.x*256 + threadIdx.x;
    if (idx >= BL*DI) return;
    int d = idx & 127, bl = idx >> 7, l = bl & (LL-1);
    size_t base = (size_t)bl*256 + d;
    float acc = cb[d];
#pragma unroll
    for (int k=0;k<4;k++) {
        int lsrc = l - 3 + k;
        float v = (lsrc >= 0) ? xz[base + (size_t)(k-3)*256] : 0.f;
        acc = fmaf(cw[d*4+k], v, acc);
    }
    float sig = 1.f/(1.f+__expf(-acc));
    xc[idx] = acc*sig;
}

__global__ void dt_proj_k(const float* __restrict__ dbc, const float* __restrict__ Wdt,
                          const float* __restrict__ bdt, float* __restrict__ dt)
{
    int idx = blockIdx.x*256 + threadIdx.x;
    if (idx >= BL*DI) return;
    int d = idx & 127, bl = idx >> 7;
    const float* row = dbc + (size_t)bl*36;
    float s = bdt[d];
#pragma unroll
    for (int r=0;r<4;r++) s = fmaf(row[r], Wdt[r*128+d], s);
    dt[idx] = (s > 20.f) ? s : log1pf(__expf(s));
}

__global__ void scan1_k(const float* __restrict__ dt, const float* __restrict__ xc,
                        const float* __restrict__ dbc, const float* __restrict__ A_log,
                        float* __restrict__ hloc, float* __restrict__ cdout)
{
    int warp = threadIdx.x >> 5;
    int wg   = (blockIdx.x<<3) + warp;
    int lane = threadIdx.x & 31;
    int s = lane & 15, half = lane >> 4;
    int dpair = wg & 63, chunk = (wg>>6) & 63, b = wg>>12;
    int d = (dpair<<1) + half;
    float Aval = -__expf(A_log[d*16+s]);
    float h = 0.f, cd = 0.f;
    size_t rowbase = (size_t)b*LL + (chunk<<8);
    const float* dtp = dt  + rowbase*128 + d;
    const float* xcp = xc  + rowbase*128 + d;
    const float* bp  = dbc + rowbase*36 + 4 + s;
#pragma unroll 8
    for (int t=0;t<CHKS;t++) {
        float dtv = dtp[t*128], xcv = xcp[t*128], Bv = bp[t*36];
        h = fmaf(h, __expf(dtv*Aval), dtv*xcv*Bv);
        cd += dtv;
    }
    int cidx = (b*128+d)*NCHK + chunk;
    hloc[cidx*16+s] = h;
    if (s == 0 ) cdout[cidx] = cd;
}

__global__ void carry_k(const float* __restrict__ hloc, const float* __restrict__ cd,
                        const float* __restrict__ A_log, float* __restrict__ Hst)
{
    int idx = blockIdx.x*256 + threadIdx.x;
    if (idx >= BB*DI*DS) return;
    int s = idx & 15, d = (idx>>4)&127, b = idx>>11;
    float Aval = -__expf(A_log[d*16+s]);
    float H = 0.f;
    int base = (b*128+d)*NCHK;
    for (int c=0;c<NCHK;c++) {
        Hst[(base+c)*16+s] = H;
        H = fmaf(H, __expf(Aval*cd[base+c]), hloc[(base+c)*16+s]);
    }
}

__global__ void scan2_k(const float* __restrict__ dt, const float* __restrict__ xc,
                        const float* __restrict__ dbc, const float* __restrict__ A_log,
                        const float* __restrict__ Hst, const float* __restrict__ xz,
                        const float* __restrict__ Dvec, float* __restrict__ ygt)
{
    __shared__ float shy[8][2][CHKS];
    int warp = threadIdx.x >> 5;
    int wg   = (blockIdx.x<<3) + warp;
    int lane = threadIdx.x & 31;
    int s = lane & 15, half = lane >> 4;
    int dpair = wg & 63, chunk = (wg>>6) & 63, b = wg>>12;
    int d = (dpair<<1) + half;
    float Aval = -__expf(A_log[d*16+s]);
    float h = Hst[((b*128+d)*NCHK + chunk)*16 + s];
    float Dv = Dvec[d];
    int t0 = chunk<<8;
    size_t rowbase = (size_t)b*LL + t0;
    const float* dtp = dt  + rowbase*128 + d;
    const float* xcp = xc  + rowbase*128 + d;
    const float* bp  = dbc + rowbase*36 + 4 + s;
    const float* cp  = dbc + rowbase*36 + 20 + s;
    const float* zp  = xz  + rowbase*256 + 128 + d;
#pragma unroll 4
    for (int t=0;t<CHKS;t++) {
        float dtv = dtp[t*128], xcv = xcp[t*128], Bv = bp[t*36], Cv = cp[t*36];
        h = fmaf(h, __expf(dtv*Aval), dtv*xcv*Bv);
        float p = h*Cv;
        p += __shfl_xor_sync(0xffffffffu, p, 1);
        p += __shfl_xor_sync(0xffffffffu, p, 2);
        p += __shfl_xor_sync(0xffffffffu, p, 4);
        p += __shfl_xor_sync(0xffffffffu, p, 8);
        if (s == 0) {
            float zv = zp[(size_t)t*256];
            float y = fmaf(xcv, Dv, p);
            float sig = 1.f/(1.f+__expf(-zv));
            shy[warp][half][t] = y*zv*sig;
        }
    }
    __syncwarp();
#pragma unroll
    for (int r=0;r<2;r++) {
        int dd = (dpair<<1) + r;
        float* dst = ygt + ((size_t)b*128 + dd)*LL + t0;
        for (int t=lane;t<CHKS;t+=32) dst[t] = shy[warp][r][t];
    }
}

__global__ void mag_k(const float* __restrict__ re, const float* __restrict__ im,
                      float* __restrict__ mg)
{
    int i = blockIdx.x*256 + threadIdx.x;
    if (i >= NIMG*FPIX) return;
    float r = re[i], m = im[i];
    mg[i] = sqrtf(r*r + m*m);
}

__global__ void phase_k(const float* __restrict__ re, const float* __restrict__ im,
                        const float* __restrict__ mg, const float* __restrict__ M2,
                        float* __restrict__ Zr, float* __restrict__ Zi)
{
    int i = blockIdx.x*256 + threadIdx.x;
    if (i >= NIMG*FPIX) return;
    float m = mg[i], m2 = M2[i];
    if (m > 1e-20f) {
        float sc = m2/m;
        Zr[i] = re[i]*sc; Zi[i] = im[i]*sc;
    } else { Zr[i] = m2; Zi[i] = 0.f; }
}

__global__ void add_k(float* __restrict__ dst, const float* __restrict__ src)
{
    int i = blockIdx.x*256 + threadIdx.x;
    if (i < BB*CC*LL) dst[i] += src[i];
}

#define GRID(BM,BN,M,N,batch) dim3(((N)+(BN)-1)/(BN), ((M)+(BM)-1)/(BM), (batch))

extern "C" void kernel_launch(void* const* d_in, const int* in_sizes, int n_in,
                              void* d_out, int out_size)
{
    const float* x      = (const float*)d_in[0];
    const float* W_in   = (const float*)d_in[1];
    const float* conv_w = (const float*)d_in[2];
    const float* conv_b = (const float*)d_in[3];
    const float* W_xproj= (const float*)d_in[4];
    const float* W_dt   = (const float*)d_in[5];
    const float* b_dt   = (const float*)d_in[6];
    const float* A_log  = (const float*)d_in[7];
    const float* Dvec   = (const float*)d_in[8];
    const float* W_out  = (const float*)d_in[9];
    const float* Wf1    = (const float*)d_in[10];
    const float* bf1    = (const float*)d_in[11];
    const float* Wf2    = (const float*)d_in[12];
    const float* bf2    = (const float*)d_in[13];
    const float* W_enh  = (const float*)d_in[14];
    const float* b_enh  = (const float*)d_in[15];
    const float* W_seg  = (const float*)d_in[16];
    const float* b_seg  = (const float*)d_in[17];
    float* out = (float*)d_out;

    void* pv;
    cudaGetSymbolAddress(&pv, d_xz);   float* p_xz  = (float*)pv;
    cudaGetSymbolAddress(&pv, d_xc);   float* p_xc  = (float*)pv;
    cudaGetSymbolAddress(&pv, d_dbc);  float* p_dbc = (float*)pv;
    cudaGetSymbolAddress(&pv, d_dt);   float* p_dt  = (float*)pv;
    cudaGetSymbolAddress(&pv, d_hloc); float* p_hl  = (float*)pv;
    cudaGetSymbolAddress(&pv, d_cd);   float* p_cd  = (float*)pv;
    cudaGetSymbolAddress(&pv, d_Hst);  float* p_Hs  = (float*)pv;
    cudaGetSymbolAddress(&pv, d_ygt);  float* p_yg  = (float*)pv;
    cudaGetSymbolAddress(&pv, d_xsp);  float* p_xsp = (float*)pv;
    cudaGetSymbolAddress(&pv, d_RT);   float* p_RT  = (float*)pv;
    cudaGetSymbolAddress(&pv, d_Cre);  float* p_Cre = (float*)pv;
    cudaGetSymbolAddress(&pv, d_Cim);  float* p_Cim = (float*)pv;
    cudaGetSymbolAddress(&pv, d_mag);  float* p_mag = (float*)pv;
    cudaGetSymbolAddress(&pv, d_M1);   float* p_M1  = (float*)pv;
    cudaGetSymbolAddress(&pv, d_M2);   float* p_M2  = (float*)pv;
    cudaGetSymbolAddress(&pv, d_Zr);   float* p_Zr  = (float*)pv;
    cudaGetSymbolAddress(&pv, d_Zi);   float* p_Zi  = (float*)pv;
    cudaGetSymbolAddress(&pv, d_Yr);   float* p_Yr  = (float*)pv;
    cudaGetSymbolAddress(&pv, d_Yi);   float* p_Yi  = (float*)pv;
    cudaGetSymbolAddress(&pv, d_xfr);  float* p_xfr = (float*)pv;
    cudaGetSymbolAddress(&pv, d_TW1);  float* p_TW1 = (float*)pv;
    cudaGetSymbolAddress(&pv, d_TCOS); float* p_TC  = (float*)pv;
    cudaGetSymbolAddress(&pv, d_TSIN); float* p_TS  = (float*)pv;
    cudaGetSymbolAddress(&pv, d_TSINN);float* p_TSN = (float*)pv;
    cudaGetSymbolAddress(&pv, d_IRW1); float* p_I1  = (float*)pv;
    cudaGetSymbolAddress(&pv, d_IRW2); float* p_I2  = (float*)pv;

    gen_tables<<<65, 256>>>();

    // ---- Mamba branch ----
    // xz[b] (L x 256) = xf[b] (L x 64) @ W_in
    sgemm<128,128,false><<<GRID(128,128,LL,256,BB),256>>>(
        x,0, 1, LL, CC*LL,  W_in,0, 256,1, 0,  p_xz, 256, LL*256,  LL, 256, CC, 0,0,0);
    conv_silu_k<<<(BL*DI+255)/256,256>>>(p_xz, conv_w, conv_b, p_xc);
    // dbc (BL x 36) = xc (BL x 128) @ W_xproj
    sgemm<128,64,false><<<GRID(128,64,BL,36,1),256>>>(
        p_xc,0, 128,1,0,  W_xproj,0, 36,1,0,  p_dbc, 36,0,  BL, 36, 128, 0,0,0);
    dt_proj_k<<<(BL*DI+255)/256,256>>>(p_dbc, W_dt, b_dt, p_dt);
    scan1_k<<<2048,256>>>(p_dt, p_xc, p_dbc, A_log, p_hl, p_cd);
    carry_k<<<32,256>>>(p_hl, p_cd, A_log, p_Hs);
    scan2_k<<<2048,256>>>(p_dt, p_xc, p_dbc, A_log, p_Hs, p_xz, Dvec, p_yg);
    // x_spatial channel-major: xsp[b](64 x L) = W_out^T @ ygt[b](128 x L)
    sgemm<64,128,false><<<GRID(64,128,CC,LL,BB),256>>>(
        W_out,0, 1, CC, 0,  p_yg,0, LL,1, DI*LL,  p_xsp, LL, CC*LL,  CC, LL, DI, 0,0,0);

    // ---- Frequency branch (DFT GEMMs) ----
    // row rfft: RT (32768 x 130) = x (32768 x 128) @ TW1
    sgemm<128,64,false><<<GRID(128,64,32768,130,1),256>>>(
        x,0, 128,1,0,  p_TW1,0, 130,1,0,  p_RT, 130,0,  32768, 130, 128, 0,0,0);
    // column FFT per image: Cre = TCOS@RTre + TSIN@RTim ; Cim = TCOS@RTim + TSINN@RTre
    sgemm<128,64,true><<<GRID(128,64,128,NKF,NIMG),256>>>(
        p_TC, p_TS,  128,1,0,  p_RT, p_RT+65, 130,1, 128*130,  p_Cre, NKF, FPIX,  128, NKF, 128, 0,0,0);
    sgemm<128,64,true><<<GRID(128,64,128,NKF,NIMG),256>>>(
        p_TC, p_TSN, 128,1,0,  p_RT+65, p_RT, 130,1, 128*130,  p_Cim, NKF, FPIX,  128, NKF, 128, 0,0,0);
    mag_k<<<(NIMG*FPIX+255)/256,256>>>(p_Cre, p_Cim, p_mag);
    // channel mix per batch: M1 = relu(Wf1 @ mag + bf1); M2 = Wf2 @ M1 + bf2
    sgemm<64,128,false><<<GRID(64,128,CC,FPIX,BB),256>>>(
        Wf1,0, CC,1,0,  p_mag,0, FPIX,1, CC*FPIX,  p_M1, FPIX, CC*FPIX,  CC, FPIX, CC, bf1, 2, 1);
    sgemm<64,128,false><<<GRID(64,128,CC,FPIX,BB),256>>>(
        Wf2,0, CC,1,0,  p_M1,0,  FPIX,1, CC*FPIX,  p_M2, FPIX, CC*FPIX,  CC, FPIX, CC, bf2, 2, 0);
    phase_k<<<(NIMG*FPIX+255)/256,256>>>(p_Cre, p_Cim, p_mag, p_M2, p_Zr, p_Zi);
    // inverse column FFT: Yr = TCOS@Zr + TSINN@Zi ; Yi = TSIN@Zr + TCOS@Zi
    sgemm<128,64,true><<<GRID(128,64,128,NKF,NIMG),256>>>(
        p_TC, p_TSN, 128,1,0,  p_Zr, p_Zi, NKF,1, FPIX,  p_Yr, NKF, FPIX,  128, NKF, 128, 0,0,0);
    sgemm<128,64,true><<<GRID(128,64,128,NKF,NIMG),256>>>(
        p_TS, p_TC,  128,1,0,  p_Zr, p_Zi, NKF,1, FPIX,  p_Yi, NKF, FPIX,  128, NKF, 128, 0,0,0);
    // irfft rows: xfr = Yr@IRW1 + Yi@IRW2   (per image, M=128 h, N=128 w, K=65)
    sgemm<128,64,true><<<GRID(128,64,128,128,NIMG),256>>>(
        p_Yr, p_Yi, NKF,1, FPIX,  p_I1, p_I2, 128,1, 0,  p_xfr, 128, LL,  128, 128, NKF, 0,0,0);

    // ---- Fuse + heads ----
    add_k<<<(BB*CC*LL+255)/256,256>>>(p_xfr, p_xsp);
    sgemm<64,128,false><<<GRID(64,128,CC,LL,BB),256>>>(
        W_enh,0, CC,1,0,  p_xfr,0, LL,1, CC*LL,  out,            LL, CC*LL,  CC, LL, CC, b_enh, 2, 0);
    sgemm<64,128,false><<<GRID(64,128,CC,LL,BB),256>>>(
        W_seg,0, CC,1,0,  p_xfr,0, LL,1, CC*LL,  out + BB*CC*LL, LL, CC*LL,  CC, LL, CC, b_seg, 2, 0);
}

// round 11
// speedup vs baseline: 1.1657x; 1.1657x over previous
#include <cuda_runtime.h>
#include <math.h>
#include <stdint.h>

#define BB 4
#define CC 64
#define LL 16384
#define BL 65536
#define DI 128
#define DS 16
#define NKF 65
#define NIMG 256
#define NCHK 64
#define CHKS 256
#define FPIX (NKF*128)   // 8320 freq pixels per image

__device__ float d_xz [BL*256];
__device__ float d_xc [BL*DI];
__device__ float d_dbc[BL*36];
__device__ float d_dt [BL*DI];
__device__ float d_hloc[BB*DI*NCHK*DS];
__device__ float d_cd  [BB*DI*NCHK];
__device__ float d_Hst [BB*DI*NCHK*DS];
__device__ float d_ygt [BB*DI*LL];
__device__ float d_xsp [BB*CC*LL];
__device__ float d_RT  [32768*130];
__device__ float d_Cre [NIMG*FPIX];
__device__ float d_Cim [NIMG*FPIX];
__device__ float d_mag [NIMG*FPIX];
__device__ float d_M1  [NIMG*FPIX];
__device__ float d_M2  [NIMG*FPIX];
__device__ float d_Zr  [NIMG*FPIX];
__device__ float d_Zi  [NIMG*FPIX];
__device__ float d_Yr  [NIMG*FPIX];
__device__ float d_Yi  [NIMG*FPIX];
__device__ float d_xfr [BB*CC*LL];
__device__ float d_TW1 [128*130];
__device__ float d_TCOS[128*128];
__device__ float d_TSIN[128*128];
__device__ float d_TSINN[128*128];
__device__ float d_IRW1[NKF*128];
__device__ float d_IRW2[NKF*128];

__global__ void gen_tables() {
    int i = blockIdx.x*256 + threadIdx.x;
    if (i < 128*130) {
        int w = i/130, j = i%130;
        int k = (j < NKF) ? j : j-NKF;
        float s,c; sincospif((float)((w*k)&127)/64.0f, &s, &c);
        d_TW1[i] = (j < NKF) ? c : -s;
    }
    if (i < 128*128) {
        int u = i/128, h = i%128;
        float s,c; sincospif((float)((u*h)&127)/64.0f, &s, &c);
        d_TCOS[i]=c; d_TSIN[i]=s; d_TSINN[i]=-s;
    }
    if (i < NKF*128) {
        int kf = i/128, w = i%128;
        float a = (kf==0 || kf==64) ? 1.0f : 2.0f;
        float s,c; sincospif((float)((kf*w)&127)/64.0f, &s, &c);
        d_IRW1[i] =  a*c*(1.0f/16384.0f);
        d_IRW2[i] = -a*s*(1.0f/16384.0f);
    }
}

// ---------------------------------------------------------------------------
// 3xTF32 tensor-core GEMM: fp32 accuracy via hi/lo error compensation.
// C[m,n] = sum_k A[m,k]*B[k,n] (+ A2*B2 if DUAL)
// 256 threads = 8 warps, warp tile 32x32 = 2x4 m16n8k8 fragments.
// ---------------------------------------------------------------------------
__device__ __forceinline__ uint32_t f2tf(float x) {
    uint32_t u; asm("cvt.rna.tf32.f32 %0, %1;" : "=r"(u) : "f"(x)); return u;
}
__device__ __forceinline__ void split_tf(float x, uint32_t& hi, uint32_t& lo) {
    hi = f2tf(x);
    lo = f2tf(x - __uint_as_float(hi));
}
__device__ __forceinline__ void mma8(float* c, const uint32_t* a, const uint32_t* b) {
    asm volatile("mma.sync.aligned.m16n8k8.row.col.f32.tf32.tf32.f32 "
                 "{%0,%1,%2,%3}, {%4,%5,%6,%7}, {%8,%9}, {%0,%1,%2,%3};\n"
                 : "+f"(c[0]), "+f"(c[1]), "+f"(c[2]), "+f"(c[3])
                 : "r"(a[0]), "r"(a[1]), "r"(a[2]), "r"(a[3]),
                   "r"(b[0]), "r"(b[1]));
}

template<int BM, int BN, int WGM, int WGN, bool DUAL>
__global__ void __launch_bounds__(256, 2)
tgemm(const float* __restrict__ A, const float* __restrict__ A2,
      int lda_m, int lda_k, int sA,
      const float* __restrict__ B, const float* __restrict__ B2,
      int ldb_k, int ldb_n, int sB,
      float* __restrict__ C, int ldc, int sC,
      int M, int N, int K,
      const float* __restrict__ bias, int biasMode, int doRelu)
{
    constexpr int PA = BM + 4, PB = BN + 4;
    __shared__ float As [16][PA];
    __shared__ float Bs [16][PB];
    __shared__ float As2[DUAL?16:1][DUAL?PA:1];
    __shared__ float Bs2[DUAL?16:1][DUAL?PB:1];

    int bz = blockIdx.z;
    const float* Ab  = A  + (size_t)bz*sA;
    const float* Bb  = B  + (size_t)bz*sB;
    const float* A2b = DUAL ? (A2 + (size_t)bz*sA) : A;
    const float* B2b = DUAL ? (B2 + (size_t)bz*sB) : B;
    float* Cb = C + (size_t)bz*sC;

    int m0 = blockIdx.y*BM, n0 = blockIdx.x*BN;
    int tid = threadIdx.x;
    int warp = tid >> 5, lane = tid & 31;
    int g = lane >> 2, q = lane & 3;
    int m_warp = (warp / WGN) * 32;
    int n_warp = (warp % WGN) * 32;

    float acc[2][4][4];
#pragma unroll
    for (int i=0;i<2;i++)
#pragma unroll
        for (int j=0;j<4;j++)
#pragma unroll
            for (int e=0;e<4;e++) acc[i][j][e] = 0.f;

    for (int k0 = 0; k0 < K; k0 += 16) {
        // ---- load A tile: As[k][m] ----
        if (lda_k == 1) {
#pragma unroll
            for (int r = 0; r < BM/16; r++) {
                int idx = tid + r*256;
                int k = idx & 15, m = idx >> 4;
                int gm = m0+m, gk = k0+k;
                bool ok = (gm < M) && (gk < K);
                As[k][m] = ok ? Ab[(size_t)gm*lda_m + gk] : 0.f;
                if (DUAL) As2[k][m] = ok ? A2b[(size_t)gm*lda_m + gk] : 0.f;
            }
        } else {
#pragma unroll
            for (int r = 0; r < BM/16; r++) {
                int idx = tid + r*256;
                int m = idx & (BM-1), k = idx / BM;
                int gm = m0+m, gk = k0+k;
                bool ok = (gm < M) && (gk < K);
                As[k][m] = ok ? Ab[(size_t)gm*lda_m + (size_t)gk*lda_k] : 0.f;
                if (DUAL) As2[k][m] = ok ? A2b[(size_t)gm*lda_m + (size_t)gk*lda_k] : 0.f;
            }
        }
        // ---- load B tile: Bs[k][n] ----
        if (ldb_n == 1) {
#pragma unroll
            for (int r = 0; r < BN/16; r++) {
                int idx = tid + r*256;
                int n = idx & (BN-1), k = idx / BN;
                int gn = n0+n, gk = k0+k;
                bool ok = (gk < K) && (gn < N);
                Bs[k][n] = ok ? Bb[(size_t)gk*ldb_k + gn] : 0.f;
                if (DUAL) Bs2[k][n] = ok ? B2b[(size_t)gk*ldb_k + gn] : 0.f;
            }
        } else {
#pragma unroll
            for (int r = 0; r < BN/16; r++) {
                int idx = tid + r*256;
                int k = idx & 15, n = idx >> 4;
                int gn = n0+n, gk = k0+k;
                bool ok = (gk < K) && (gn < N);
                Bs[k][n] = ok ? Bb[(size_t)gk*ldb_k + (size_t)gn*ldb_n] : 0.f;
                if (DUAL) Bs2[k][n] = ok ? B2b[(size_t)gk*ldb_k + (size_t)gn*ldb_n] : 0.f;
            }
        }
        __syncthreads();
#pragma unroll
        for (int k8 = 0; k8 < 16; k8 += 8) {
            uint32_t ah[2][4], al[2][4], bh[4][2], blr[4][2];
#pragma unroll
            for (int mt=0; mt<2; mt++) {
                int mA = m_warp + mt*16;
                split_tf(As[k8+q  ][mA+g  ], ah[mt][0], al[mt][0]);
                split_tf(As[k8+q  ][mA+g+8], ah[mt][1], al[mt][1]);
                split_tf(As[k8+q+4][mA+g  ], ah[mt][2], al[mt][2]);
                split_tf(As[k8+q+4][mA+g+8], ah[mt][3], al[mt][3]);
            }
#pragma unroll
            for (int nt=0; nt<4; nt++) {
                int nB = n_warp + nt*8;
                split_tf(Bs[k8+q  ][nB+g], bh[nt][0], blr[nt][0]);
                split_tf(Bs[k8+q+4][nB+g], bh[nt][1], blr[nt][1]);
            }
#pragma unroll
            for (int mt=0; mt<2; mt++)
#pragma unroll
                for (int nt=0; nt<4; nt++) {
                    mma8(acc[mt][nt], al[mt], bh[nt]);
                    mma8(acc[mt][nt], ah[mt], blr[nt]);
                    mma8(acc[mt][nt], ah[mt], bh[nt]);
                }
            if (DUAL) {
#pragma unroll
                for (int mt=0; mt<2; mt++) {
                    int mA = m_warp + mt*16;
                    split_tf(As2[k8+q  ][mA+g  ], ah[mt][0], al[mt][0]);
                    split_tf(As2[k8+q  ][mA+g+8], ah[mt][1], al[mt][1]);
                    split_tf(As2[k8+q+4][mA+g  ], ah[mt][2], al[mt][2]);
                    split_tf(As2[k8+q+4][mA+g+8], ah[mt][3], al[mt][3]);
                }
#pragma unroll
                for (int nt=0; nt<4; nt++) {
                    int nB = n_warp + nt*8;
                    split_tf(Bs2[k8+q  ][nB+g], bh[nt][0], blr[nt][0]);
                    split_tf(Bs2[k8+q+4][nB+g], bh[nt][1], blr[nt][1]);
                }
#pragma unroll
                for (int mt=0; mt<2; mt++)
#pragma unroll
                    for (int nt=0; nt<4; nt++) {
                        mma8(acc[mt][nt], al[mt], bh[nt]);
                        mma8(acc[mt][nt], ah[mt], blr[nt]);
                        mma8(acc[mt][nt], ah[mt], bh[nt]);
                    }
            }
        }
        __syncthreads();
    }
    // ---- epilogue ----
#pragma unroll
    for (int mt=0; mt<2; mt++) {
#pragma unroll
        for (int nt=0; nt<4; nt++) {
            int mbase = m0 + m_warp + mt*16 + g;
            int nbase = n0 + n_warp + nt*8 + q*2;
#pragma unroll
            for (int e=0; e<4; e++) {
                int m = mbase + ((e >= 2) ? 8 : 0);
                int n = nbase + (e & 1);
                if (m < M && n < N) {
                    float v = acc[mt][nt][e];
                    if (biasMode == 1) v += bias[n];
                    else if (biasMode == 2) v += bias[m];
                    if (doRelu) v = fmaxf(v, 0.f);
                    Cb[(size_t)m*ldc + n] = v;
                }
            }
        }
    }
}

__global__ void conv_silu_k(const float* __restrict__ xz, const float* __restrict__ cw,
                            const float* __restrict__ cb, float* __restrict__ xc)
{
    int idx = blockIdx.x*256 + threadIdx.x;
    if (idx >= BL*DI) return;
    int d = idx & 127, bl = idx >> 7, l = bl & (LL-1);
    size_t base = (size_t)bl*256 + d;
    float acc = cb[d];
#pragma unroll
    for (int k=0;k<4;k++) {
        int lsrc = l - 3 + k;
        float v = (lsrc >= 0) ? xz[base + (size_t)(k-3)*256] : 0.f;
        acc = fmaf(cw[d*4+k], v, acc);
    }
    float sig = 1.f/(1.f+__expf(-acc));
    xc[idx] = acc*sig;
}

__global__ void dt_proj_k(const float* __restrict__ dbc, const float* __restrict__ Wdt,
                          const float* __restrict__ bdt, float* __restrict__ dt)
{
    int idx = blockIdx.x*256 + threadIdx.x;
    if (idx >= BL*DI) return;
    int d = idx & 127, bl = idx >> 7;
    const float* row = dbc + (size_t)bl*36;
    float s = bdt[d];
#pragma unroll
    for (int r=0;r<4;r++) s = fmaf(row[r], Wdt[r*128+d], s);
    dt[idx] = (s > 20.f) ? s : log1pf(__expf(s));
}

__global__ void scan1_k(const float* __restrict__ dt, const float* __restrict__ xc,
                        const float* __restrict__ dbc, const float* __restrict__ A_log,
                        float* __restrict__ hloc, float* __restrict__ cdout)
{
    int warp = threadIdx.x >> 5;
    int wg   = (blockIdx.x<<3) + warp;
    int lane = threadIdx.x & 31;
    int s = lane & 15, half = lane >> 4;
    int dpair = wg & 63, chunk = (wg>>6) & 63, b = wg>>12;
    int d = (dpair<<1) + half;
    float Aval = -__expf(A_log[d*16+s]);
    float h = 0.f, cd = 0.f;
    size_t rowbase = (size_t)b*LL + (chunk<<8);
    const float* dtp = dt  + rowbase*128 + d;
    const float* xcp = xc  + rowbase*128 + d;
    const float* bp  = dbc + rowbase*36 + 4 + s;
#pragma unroll 8
    for (int t=0;t<CHKS;t++) {
        float dtv = dtp[t*128], xcv = xcp[t*128], Bv = bp[t*36];
        h = fmaf(h, __expf(dtv*Aval), dtv*xcv*Bv);
        cd += dtv;
    }
    int cidx = (b*128+d)*NCHK + chunk;
    hloc[cidx*16+s] = h;
    if (s == 0 ) cdout[cidx] = cd;
}

__global__ void carry_k(const float* __restrict__ hloc, const float* __restrict__ cd,
                        const float* __restrict__ A_log, float* __restrict__ Hst)
{
    int idx = blockIdx.x*256 + threadIdx.x;
    if (idx >= BB*DI*DS) return;
    int s = idx & 15, d = (idx>>4)&127, b = idx>>11;
    float Aval = -__expf(A_log[d*16+s]);
    float H = 0.f;
    int base = (b*128+d)*NCHK;
    for (int c=0;c<NCHK;c++) {
        Hst[(base+c)*16+s] = H;
        H = fmaf(H, __expf(Aval*cd[base+c]), hloc[(base+c)*16+s]);
    }
}

__global__ void scan2_k(const float* __restrict__ dt, const float* __restrict__ xc,
                        const float* __restrict__ dbc, const float* __restrict__ A_log,
                        const float* __restrict__ Hst, const float* __restrict__ xz,
                        const float* __restrict__ Dvec, float* __restrict__ ygt)
{
    __shared__ float shy[8][2][CHKS];
    int warp = threadIdx.x >> 5;
    int wg   = (blockIdx.x<<3) + warp;
    int lane = threadIdx.x & 31;
    int s = lane & 15, half = lane >> 4;
    int dpair = wg & 63, chunk = (wg>>6) & 63, b = wg>>12;
    int d = (dpair<<1) + half;
    float Aval = -__expf(A_log[d*16+s]);
    float h = Hst[((b*128+d)*NCHK + chunk)*16 + s];
    float Dv = Dvec[d];
    int t0 = chunk<<8;
    size_t rowbase = (size_t)b*LL + t0;
    const float* dtp = dt  + rowbase*128 + d;
    const float* xcp = xc  + rowbase*128 + d;
    const float* bp  = dbc + rowbase*36 + 4 + s;
    const float* cp  = dbc + rowbase*36 + 20 + s;
    const float* zp  = xz  + rowbase*256 + 128 + d;
#pragma unroll 4
    for (int t=0;t<CHKS;t++) {
        float dtv = dtp[t*128], xcv = xcp[t*128], Bv = bp[t*36], Cv = cp[t*36];
        h = fmaf(h, __expf(dtv*Aval), dtv*xcv*Bv);
        float p = h*Cv;
        p += __shfl_xor_sync(0xffffffffu, p, 1);
        p += __shfl_xor_sync(0xffffffffu, p, 2);
        p += __shfl_xor_sync(0xffffffffu, p, 4);
        p += __shfl_xor_sync(0xffffffffu, p, 8);
        if (s == 0) {
            float zv = zp[(size_t)t*256];
            float y = fmaf(xcv, Dv, p);
            float sig = 1.f/(1.f+__expf(-zv));
            shy[warp][half][t] = y*zv*sig;
        }
    }
    __syncwarp();
#pragma unroll
    for (int r=0;r<2;r++) {
        int dd = (dpair<<1) + r;
        float* dst = ygt + ((size_t)b*128 + dd)*LL + t0;
        for (int t=lane;t<CHKS;t+=32) dst[t] = shy[warp][r][t];
    }
}

__global__ void mag_k(const float* __restrict__ re, const float* __restrict__ im,
                      float* __restrict__ mg)
{
    int i = blockIdx.x*256 + threadIdx.x;
    if (i >= NIMG*FPIX) return;
    float r = re[i], m = im[i];
    mg[i] = sqrtf(r*r + m*m);
}

__global__ void phase_k(const float* __restrict__ re, const float* __restrict__ im,
                        const float* __restrict__ mg, const float* __restrict__ M2,
                        float* __restrict__ Zr, float* __restrict__ Zi)
{
    int i = blockIdx.x*256 + threadIdx.x;
    if (i >= NIMG*FPIX) return;
    float m = mg[i], m2 = M2[i];
    if (m > 1e-20f) {
        float sc = m2/m;
        Zr[i] = re[i]*sc; Zi[i] = im[i]*sc;
    } else { Zr[i] = m2; Zi[i] = 0.f; }
}

__global__ void add_k(float* __restrict__ dst, const float* __restrict__ src)
{
    int i = blockIdx.x*256 + threadIdx.x;
    if (i < BB*CC*LL) dst[i] += src[i];
}

#define GR(BM,BN,M,N,batch) dim3(((N)+(BN)-1)/(BN), ((M)+(BM)-1)/(BM), (batch))

extern "C" void kernel_launch(void* const* d_in, const int* in_sizes, int n_in,
                              void* d_out, int out_size)
{
    const float* x      = (const float*)d_in[0];
    const float* W_in   = (const float*)d_in[1];
    const float* conv_w = (const float*)d_in[2];
    const float* conv_b = (const float*)d_in[3];
    const float* W_xproj= (const float*)d_in[4];
    const float* W_dt   = (const float*)d_in[5];
    const float* b_dt   = (const float*)d_in[6];
    const float* A_log  = (const float*)d_in[7];
    const float* Dvec   = (const float*)d_in[8];
    const float* W_out  = (const float*)d_in[9];
    const float* Wf1    = (const float*)d_in[10];
    const float* bf1    = (const float*)d_in[11];
    const float* Wf2    = (const float*)d_in[12];
    const float* bf2    = (const float*)d_in[13];
    const float* W_enh  = (const float*)d_in[14];
    const float* b_enh  = (const float*)d_in[15];
    const float* W_seg  = (const float*)d_in[16];
    const float* b_seg  = (const float*)d_in[17];
    float* out = (float*)d_out;

    void* pv;
    cudaGetSymbolAddress(&pv, d_xz);   float* p_xz  = (float*)pv;
    cudaGetSymbolAddress(&pv, d_xc);   float* p_xc  = (float*)pv;
    cudaGetSymbolAddress(&pv, d_dbc);  float* p_dbc = (float*)pv;
    cudaGetSymbolAddress(&pv, d_dt);   float* p_dt  = (float*)pv;
    cudaGetSymbolAddress(&pv, d_hloc); float* p_hl  = (float*)pv;
    cudaGetSymbolAddress(&pv, d_cd);   float* p_cd  = (float*)pv;
    cudaGetSymbolAddress(&pv, d_Hst);  float* p_Hs  = (float*)pv;
    cudaGetSymbolAddress(&pv, d_ygt);  float* p_yg  = (float*)pv;
    cudaGetSymbolAddress(&pv, d_xsp);  float* p_xsp = (float*)pv;
    cudaGetSymbolAddress(&pv, d_RT);   float* p_RT  = (float*)pv;
    cudaGetSymbolAddress(&pv, d_Cre);  float* p_Cre = (float*)pv;
    cudaGetSymbolAddress(&pv, d_Cim);  float* p_Cim = (float*)pv;
    cudaGetSymbolAddress(&pv, d_mag);  float* p_mag = (float*)pv;
    cudaGetSymbolAddress(&pv, d_M1);   float* p_M1  = (float*)pv;
    cudaGetSymbolAddress(&pv, d_M2);   float* p_M2  = (float*)pv;
    cudaGetSymbolAddress(&pv, d_Zr);   float* p_Zr  = (float*)pv;
    cudaGetSymbolAddress(&pv, d_Zi);   float* p_Zi  = (float*)pv;
    cudaGetSymbolAddress(&pv, d_Yr);   float* p_Yr  = (float*)pv;
    cudaGetSymbolAddress(&pv, d_Yi);   float* p_Yi  = (float*)pv;
    cudaGetSymbolAddress(&pv, d_xfr);  float* p_xfr = (float*)pv;
    cudaGetSymbolAddress(&pv, d_TW1);  float* p_TW1 = (float*)pv;
    cudaGetSymbolAddress(&pv, d_TCOS); float* p_TC  = (float*)pv;
    cudaGetSymbolAddress(&pv, d_TSIN); float* p_TS  = (float*)pv;
    cudaGetSymbolAddress(&pv, d_TSINN);float* p_TSN = (float*)pv;
    cudaGetSymbolAddress(&pv, d_IRW1); float* p_I1  = (float*)pv;
    cudaGetSymbolAddress(&pv, d_IRW2); float* p_I2  = (float*)pv;

    gen_tables<<<65, 256>>>();

    // ---- Mamba branch ----
    // xz[b] (L x 256) = xf[b] (L x 64) @ W_in
    tgemm<128,64,4,2,false><<<GR(128,64,LL,256,BB),256>>>(
        x,0, 1, LL, CC*LL,  W_in,0, 256,1, 0,  p_xz, 256, LL*256,  LL, 256, CC, 0,0,0);
    conv_silu_k<<<(BL*DI+255)/256,256>>>(p_xz, conv_w, conv_b, p_xc);
    // dbc (BL x 36) = xc (BL x 128) @ W_xproj
    tgemm<128,64,4,2,false><<<GR(128,64,BL,36,1),256>>>(
        p_xc,0, 128,1,0,  W_xproj,0, 36,1,0,  p_dbc, 36,0,  BL, 36, 128, 0,0,0);
    dt_proj_k<<<(BL*DI+255)/256,256>>>(p_dbc, W_dt, b_dt, p_dt);
    scan1_k<<<2048,256>>>(p_dt, p_xc, p_dbc, A_log, p_hl, p_cd);
    carry_k<<<32,256>>>(p_hl, p_cd, A_log, p_Hs);
    scan2_k<<<2048,256>>>(p_dt, p_xc, p_dbc, A_log, p_Hs, p_xz, Dvec, p_yg);
    // x_spatial channel-major: xsp[b](64 x L) = W_out^T @ ygt[b](128 x L)
    tgemm<64,128,2,4,false><<<GR(64,128,CC,LL,BB),256>>>(
        W_out,0, 1, CC, 0,  p_yg,0, LL,1, DI*LL,  p_xsp, LL, CC*LL,  CC, LL, DI, 0,0,0);

    // ---- Frequency branch (DFT GEMMs) ----
    // row rfft: RT (32768 x 130) = x (32768 x 128) @ TW1
    tgemm<128,64,4,2,false><<<GR(128,64,32768,130,1),256>>>(
        x,0, 128,1,0,  p_TW1,0, 130,1,0,  p_RT, 130,0,  32768, 130, 128, 0,0,0);
    // column FFT per image: Cre = TCOS@RTre + TSIN@RTim ; Cim = TCOS@RTim + TSINN@RTre
    tgemm<128,64,4,2,true><<<GR(128,64,128,NKF,NIMG),256>>>(
        p_TC, p_TS,  128,1,0,  p_RT, p_RT+65, 130,1, 128*130,  p_Cre, NKF, FPIX,  128, NKF, 128, 0,0,0);
    tgemm<128,64,4,2,true><<<GR(128,64,128,NKF,NIMG),256>>>(
        p_TC, p_TSN, 128,1,0,  p_RT+65, p_RT, 130,1, 128*130,  p_Cim, NKF, FPIX,  128, NKF, 128, 0,0,0);
    mag_k<<<(NIMG*FPIX+255)/256,256>>>(p_Cre, p_Cim, p_mag);
    // channel mix per batch: M1 = relu(Wf1 @ mag + bf1); M2 = Wf2 @ M1 + bf2
    tgemm<64,128,2,4,false><<<GR(64,128,CC,FPIX,BB),256>>>(
        Wf1,0, CC,1,0,  p_mag,0, FPIX,1, CC*FPIX,  p_M1, FPIX, CC*FPIX,  CC, FPIX, CC, bf1, 2, 1);
    tgemm<64,128,2,4,false><<<GR(64,128,CC,FPIX,BB),256>>>(
        Wf2,0, CC,1,0,  p_M1,0,  FPIX,1, CC*FPIX,  p_M2, FPIX, CC*FPIX,  CC, FPIX, CC, bf2, 2, 0);
    phase_k<<<(NIMG*FPIX+255)/256,256>>>(p_Cre, p_Cim, p_mag, p_M2, p_Zr, p_Zi);
    // inverse column FFT: Yr = TCOS@Zr + TSINN@Zi ; Yi = TSIN@Zr + TCOS@Zi
    tgemm<128,64,4,2,true><<<GR(128,64,128,NKF,NIMG),256>>>(
        p_TC, p_TSN, 128,1,0,  p_Zr, p_Zi, NKF,1, FPIX,  p_Yr, NKF, FPIX,  128, NKF, 128, 0,0,0);
    tgemm<128,64,4,2,true><<<GR(128,64,128,NKF,NIMG),256>>>(
        p_TS, p_TC,  128,1,0,  p_Zr, p_Zi, NKF,1, FPIX,  p_Yi, NKF, FPIX,  128, NKF, 128, 0,0,0);
    // irfft rows: xfr = Yr@IRW1 + Yi@IRW2   (per image, M=128 h, N=128 w, K=65)
    tgemm<128,64,4,2,true><<<GR(128,64,128,128,NIMG),256>>>(
        p_Yr, p_Yi, NKF,1, FPIX,  p_I1, p_I2, 128,1, 0,  p_xfr, 128, LL,  128, 128, NKF, 0,0,0);

    // ---- Fuse + heads ----
    add_k<<<(BB*CC*LL+255)/256,256>>>(p_xfr, p_xsp);
    tgemm<64,128,2,4,false><<<GR(64,128,CC,LL,BB),256>>>(
        W_enh,0, CC,1,0,  p_xfr,0, LL,1, CC*LL,  out,            LL, CC*LL,  CC, LL, CC, b_enh, 2, 0);
    tgemm<64,128,2,4,false><<<GR(64,128,CC,LL,BB),256>>>(
        W_seg,0, CC,1,0,  p_xfr,0, LL,1, CC*LL,  out + BB*CC*LL, LL, CC*LL,  CC, LL, CC, b_seg, 2, 0);
}